// round 13
// baseline (speedup 1.0000x reference)
#include <cuda_runtime.h>
#include <cuda_bf16.h>
#include <cstdint>

// Problem constants (fixed by the reference setup)
#define N_NODES   128
#define CAL_N     256
#define N_OBS     64
#define SPB       128    // samples per block in main kernel
#define NTHR      32     // 1 warp; each thread owns 4 consecutive samples
#define CHUNK     8      // node-rows per staging chunk
#define NCHUNK    (N_NODES / CHUNK)   // 16
#define DEPTH     4      // cp.async pipeline depth (chunks in flight)

// Device scratch (allocation-free rule: __device__ globals)
__device__ float4       g_cA[N_NODES];   // {w0, w1, b, sigma} (root: {0,0,0,1})
__device__ uint32_t     g_cPk[N_NODES];  // (p0*SPB*4) | ((p1*SPB*4)<<16); UNSIGNED so
                                         // >>16 is a logical shift
__device__ const float* g_srcP[N_NODES]; // per-node source row: root->rm+i*n else zn+i*n

__device__ __forceinline__ uint32_t smem_u32(const void* p) {
    return (uint32_t)__cvta_generic_to_shared(p);
}

// ---------------------------------------------------------------------------
// K1 (fused cal): 128 blocks x 256 threads. EVERY block redundantly runs the
// noiseless pilot recurrence over [128 nodes][256 samples] in its own smem
// (identical FP ops -> identical result), then block b rank-counts its own
// node b and bakes the per-node constants for the main pass.
// jnp.quantile linear: q25 at 63.75 -> v[63]+0.75*(v[64]-v[63]),
//                      q75 at 191.25 -> v[191]+0.25*(v[192]-v[191]).
// ---------------------------------------------------------------------------
__global__ void __launch_bounds__(CAL_N)
cal_kernel(const float* __restrict__ W,
           const float* __restrict__ b,
           const float* __restrict__ pm,
           const int*   __restrict__ pidx,
           const float* __restrict__ root_pilot,
           const float* __restrict__ rm,
           const float* __restrict__ zn,
           int n)
{
    extern __shared__ float xs[];          // [N_NODES][CAL_N] = 128 KB
    __shared__ float4 pc[N_NODES];
    __shared__ int    pp[N_NODES];
    __shared__ float  q[4];

    int node = blockIdx.x;
    int t = threadIdx.x;

    if (t < N_NODES) {
        float m0 = pm[t * 2 + 0], m1 = pm[t * 2 + 1];
        bool  root = (m0 == 0.f) && (m1 == 0.f);
        pc[t] = make_float4(W[t * 2 + 0] * m0, W[t * 2 + 1] * m1,
                            b[t], root ? 1.f : 0.f);
        pp[t] = (pidx[t * 2 + 0] & 0xff) | ((pidx[t * 2 + 1] & 0xff) << 8);
    }
    __syncthreads();

    for (int i = 0; i < N_NODES; i++) {
        float4 c  = pc[i];
        int    pk = pp[i];
        float v;
        if (c.w != 0.f) {
            v = root_pilot[i * CAL_N + t];
        } else {
            float pv0 = xs[(pk & 0xff) * CAL_N + t];
            float pv1 = xs[((pk >> 8) & 0xff) * CAL_N + t];
            v = fmaxf(fmaf(c.x, pv0, fmaf(c.y, pv1, c.z)), 0.f);
        }
        xs[i * CAL_N + t] = v;
    }

    float my = xs[node * CAL_N + t];
    __syncthreads();

    const float* row = xs + node * CAL_N;
    int rank = 0;
    #pragma unroll 8
    for (int j = 0; j < CAL_N; j++) {
        float o = row[j];
        rank += (o < my) || (o == my && j < t);   // stable rank: bijection 0..255
    }
    if (rank == 63)  q[0] = my;
    if (rank == 64)  q[1] = my;
    if (rank == 191) q[2] = my;
    if (rank == 192) q[3] = my;
    __syncthreads();

    if (t == 0) {
        float q25 = q[0] + 0.75f * (q[1] - q[0]);
        float q75 = q[2] + 0.25f * (q[3] - q[2]);
        float sig = 0.1f * fmaxf(q75 - q25, 1e-6f);

        float m0 = pm[node * 2 + 0], m1 = pm[node * 2 + 1];
        bool  root = (m0 == 0.f) && (m1 == 0.f);
        uint32_t p0 = (uint32_t)(pidx[node * 2 + 0] & 0xff) * (SPB * 4);
        uint32_t p1 = (uint32_t)(pidx[node * 2 + 1] & 0xff) * (SPB * 4);
        if (root) {
            g_cA[node]   = make_float4(0.f, 0.f, 0.f, 1.f);
            g_cPk[node]  = 0u;
            g_srcP[node] = rm + (size_t)node * n;
        } else {
            g_cA[node]   = make_float4(W[node * 2 + 0] * m0,
                                       W[node * 2 + 1] * m1,
                                       b[node], sig);
            g_cPk[node]  = p0 | (p1 << 16);
            g_srcP[node] = zn + (size_t)node * n;
        }
    }
}

// ---------------------------------------------------------------------------
// K2: main pass, FULLY VECTORIZED. 1 warp per block, 128 samples; thread t
// owns samples 4t..4t+3, i.e. a 16B-wide private column slice of
// shv[node][128]. Every memory op is 128-bit:
//   cp.async 16B (1 LDGSTS covers 4 samples), LDS.128 stage read,
//   2x LDS.128 parent reads, STS.128 result store.
// ~4x fewer LSU instructions than the R12 scalar version, which ncu showed
// was L1/LSU-issue bound (L1 76%, DRAM only 26%). Stage slices stay
// thread-private -> zero __syncthreads in the mainloop. 2 blocks/SM x
// DEPTH(4) x 4KB chunks = 32KB cp.async in flight per SM.
//   v_i = relu(w0*pv0 + w1*pv1 + b) + sigma * src_i[s]
// Root: w=b=0, sigma=1 (fmaxf kills 0*garbage NaN) -> v = root_main exactly.
// ---------------------------------------------------------------------------
__global__ void __launch_bounds__(NTHR)
main_kernel(const int* __restrict__ chosen,
            float*     __restrict__ out,
            int n)
{
    extern __shared__ float shv[];         // [N_NODES][SPB] = 64 KB
    float* stage = shv + N_NODES * SPB;    // [DEPTH][CHUNK][SPB] = 16 KB
    __shared__ float4       cA[N_NODES];
    __shared__ uint32_t     cPk[N_NODES];
    __shared__ const float* srcP[N_NODES];
    __shared__ int          ch[N_OBS];

    int t  = threadIdx.x;
    int s0 = blockIdx.x * SPB;

    #pragma unroll
    for (int j = t; j < N_NODES; j += NTHR) {
        cA[j]   = g_cA[j];
        cPk[j]  = g_cPk[j];
        srcP[j] = g_srcP[j];
    }
    #pragma unroll
    for (int j = t; j < N_OBS; j += NTHR) ch[j] = chosen[j];
    __syncthreads();                       // one warp; publishes the tables

    char* myCol = reinterpret_cast<char*>(shv) + t * 16;   // 16B column slice
    const uint32_t myStage = smem_u32(stage) + (uint32_t)t * 16;

    if (s0 + SPB <= n) {
        // thread-private 16B cp.async: thread t fills samples 4t..4t+3 of each row
        auto prefetch = [&](int c) {
            uint32_t dst = myStage + (uint32_t)(c & (DEPTH - 1)) * (CHUNK * SPB * 4);
            #pragma unroll
            for (int r = 0; r < CHUNK; r++) {
                const float* src = srcP[c * CHUNK + r] + s0 + 4 * t;  // 16B aligned
                asm volatile("cp.async.ca.shared.global [%0], [%1], 16;\n"
                             :: "r"(dst + r * (SPB * 4)), "l"(src) : "memory");
            }
            asm volatile("cp.async.commit_group;\n" ::: "memory");
        };
        auto consume = [&](int c) {
            const char* stg = reinterpret_cast<const char*>(stage)
                              + (c & (DEPTH - 1)) * (CHUNK * SPB * 4) + t * 16;
            #pragma unroll
            for (int u = 0; u < CHUNK; u++) {
                int i = c * CHUNK + u;
                float4   cur = *reinterpret_cast<const float4*>(stg + u * (SPB * 4));
                float4   cc  = cA[i];                 // uniform LDS.128 broadcast
                uint32_t pk  = cPk[i];
                float4 p0 = *reinterpret_cast<const float4*>(myCol + (pk & 0xffffu));
                float4 p1 = *reinterpret_cast<const float4*>(myCol + (pk >> 16));
                float4 r;
                r.x = fmaf(cc.w, cur.x, fmaxf(fmaf(cc.x, p0.x, fmaf(cc.y, p1.x, cc.z)), 0.f));
                r.y = fmaf(cc.w, cur.y, fmaxf(fmaf(cc.x, p0.y, fmaf(cc.y, p1.y, cc.z)), 0.f));
                r.z = fmaf(cc.w, cur.z, fmaxf(fmaf(cc.x, p0.z, fmaf(cc.y, p1.z, cc.z)), 0.f));
                r.w = fmaf(cc.w, cur.w, fmaxf(fmaf(cc.x, p0.w, fmaf(cc.y, p1.w, cc.z)), 0.f));
                *reinterpret_cast<float4*>(myCol + i * (SPB * 4)) = r;
            }
        };

        prefetch(0); prefetch(1); prefetch(2); prefetch(3);

        #pragma unroll 1
        for (int c = 0; c < NCHUNK - DEPTH; c++) {
            asm volatile("cp.async.wait_group %0;\n" :: "n"(DEPTH - 1) : "memory");
            consume(c);
            prefetch(c + DEPTH);
        }
        asm volatile("cp.async.wait_group 2;\n" ::: "memory"); consume(NCHUNK - 4);
        asm volatile("cp.async.wait_group 1;\n" ::: "memory"); consume(NCHUNK - 3);
        asm volatile("cp.async.wait_group 0;\n" ::: "memory");
        consume(NCHUNK - 2); consume(NCHUNK - 1);

        // Output: 4x4 transpose gather. Thread t owns output rows s0+4t..s0+4t+3.
        // For each group of 4 chosen nodes: 4x LDS.128 (own columns) -> 4x STG.128.
        #pragma unroll 4
        for (int j0 = 0; j0 < N_OBS / 4; j0++) {
            float4 v0 = *reinterpret_cast<const float4*>(myCol + ch[4*j0+0] * (SPB*4));
            float4 v1 = *reinterpret_cast<const float4*>(myCol + ch[4*j0+1] * (SPB*4));
            float4 v2 = *reinterpret_cast<const float4*>(myCol + ch[4*j0+2] * (SPB*4));
            float4 v3 = *reinterpret_cast<const float4*>(myCol + ch[4*j0+3] * (SPB*4));
            size_t base = (size_t)(s0 + 4 * t) * N_OBS + 4 * j0;
            *reinterpret_cast<float4*>(out + base)             = make_float4(v0.x, v1.x, v2.x, v3.x);
            *reinterpret_cast<float4*>(out + base + N_OBS)     = make_float4(v0.y, v1.y, v2.y, v3.y);
            *reinterpret_cast<float4*>(out + base + 2 * N_OBS) = make_float4(v0.z, v1.z, v2.z, v3.z);
            *reinterpret_cast<float4*>(out + base + 3 * N_OBS) = make_float4(v0.w, v1.w, v2.w, v3.w);
        }
    } else {
        // ---- tail path (unused at n=262144, kept for generality) ----
        for (int k = 0; k < 4; k++) {
            int s = s0 + 4 * t + k;
            if (s >= n) break;
            for (int i = 0; i < N_NODES; i++) {
                float    cur = srcP[i][s];
                float4   cc  = cA[i];
                uint32_t pk  = cPk[i];
                float pv0 = *reinterpret_cast<float*>(myCol + (pk & 0xffffu) + 4 * k);
                float pv1 = *reinterpret_cast<float*>(myCol + (pk >> 16) + 4 * k);
                float h   = fmaxf(fmaf(cc.x, pv0, fmaf(cc.y, pv1, cc.z)), 0.f);
                *reinterpret_cast<float*>(myCol + i * (SPB * 4) + 4 * k) = fmaf(cc.w, cur, h);
            }
            for (int j = 0; j < N_OBS; j++)
                out[(size_t)s * N_OBS + j] = shv[ch[j] * SPB + 4 * t + k];
        }
    }
}

// ---------------------------------------------------------------------------
// Launch. Input order per setup_inputs dict:
// 0:n_samples 1:W 2:b 3:root_pilot 4:root_main 5:z_noise
// 6:par_mask 7:par_idx 8:is_root 9:chosen
// ---------------------------------------------------------------------------
extern "C" void kernel_launch(void* const* d_in, const int* in_sizes, int n_in,
                              void* d_out, int out_size)
{
    const float* W    = (const float*)d_in[1];
    const float* b    = (const float*)d_in[2];
    const float* rpil = (const float*)d_in[3];
    const float* rm   = (const float*)d_in[4];
    const float* zn   = (const float*)d_in[5];
    const float* pmsk = (const float*)d_in[6];
    const int*   pidx = (const int*)d_in[7];
    const int*   chos = (const int*)d_in[9];
    float*       out  = (float*)d_out;

    int n = in_sizes[4] / N_NODES;     // 262144

    const int calSmem  = N_NODES * CAL_N * sizeof(float);                    // 128 KB
    const int mainSmem = (N_NODES * SPB + DEPTH * CHUNK * SPB) * sizeof(float); // 80 KB

    cudaFuncSetAttribute(cal_kernel,
                         cudaFuncAttributeMaxDynamicSharedMemorySize, calSmem);
    cudaFuncSetAttribute(main_kernel,
                         cudaFuncAttributeMaxDynamicSharedMemorySize, mainSmem);

    cal_kernel<<<N_NODES, CAL_N, calSmem>>>(W, b, pmsk, pidx, rpil, rm, zn, n);

    int grid = (n + SPB - 1) / SPB;    // 2048
    main_kernel<<<grid, NTHR, mainSmem>>>(chos, out, n);
}

// round 15
// speedup vs baseline: 1.1435x; 1.1435x over previous
#include <cuda_runtime.h>
#include <cuda_bf16.h>
#include <cstdint>

// Problem constants (fixed by the reference setup)
#define N_NODES   128
#define CAL_N     256
#define N_OBS     64
#define SPB       64     // samples per block in main kernel
#define NTHR      32     // 1 warp; each thread owns 2 consecutive samples
#define CHUNK     8      // node-rows per staging chunk
#define NCHUNK    (N_NODES / CHUNK)   // 16
#define DEPTH     4      // cp.async pipeline depth (chunks in flight)

// Device scratch (allocation-free rule: __device__ globals)
__device__ float4       g_cA[N_NODES];   // {w0, w1, b, sigma} (root: {0,0,0,1})
__device__ uint32_t     g_cPk[N_NODES];  // (p0*SPB*4) | ((p1*SPB*4)<<16); UNSIGNED so
                                         // >>16 is a logical shift
__device__ const float* g_srcP[N_NODES]; // per-node source row: root->rm+i*n else zn+i*n

__device__ __forceinline__ uint32_t smem_u32(const void* p) {
    return (uint32_t)__cvta_generic_to_shared(p);
}

// ---------------------------------------------------------------------------
// K1 (fused cal): 128 blocks x 256 threads. EVERY block redundantly runs the
// noiseless pilot recurrence over [128 nodes][256 samples] in its own smem
// (identical FP ops -> identical result), then block b rank-counts its own
// node b and bakes the per-node constants for the main pass.
// jnp.quantile linear: q25 at 63.75 -> v[63]+0.75*(v[64]-v[63]),
//                      q75 at 191.25 -> v[191]+0.25*(v[192]-v[191]).
// ---------------------------------------------------------------------------
__global__ void __launch_bounds__(CAL_N)
cal_kernel(const float* __restrict__ W,
           const float* __restrict__ b,
           const float* __restrict__ pm,
           const int*   __restrict__ pidx,
           const float* __restrict__ root_pilot,
           const float* __restrict__ rm,
           const float* __restrict__ zn,
           int n)
{
    extern __shared__ float xs[];          // [N_NODES][CAL_N] = 128 KB
    __shared__ float4 pc[N_NODES];
    __shared__ int    pp[N_NODES];
    __shared__ float  q[4];

    int node = blockIdx.x;
    int t = threadIdx.x;

    if (t < N_NODES) {
        float m0 = pm[t * 2 + 0], m1 = pm[t * 2 + 1];
        bool  root = (m0 == 0.f) && (m1 == 0.f);
        pc[t] = make_float4(W[t * 2 + 0] * m0, W[t * 2 + 1] * m1,
                            b[t], root ? 1.f : 0.f);
        pp[t] = (pidx[t * 2 + 0] & 0xff) | ((pidx[t * 2 + 1] & 0xff) << 8);
    }
    __syncthreads();

    for (int i = 0; i < N_NODES; i++) {
        float4 c  = pc[i];
        int    pk = pp[i];
        float v;
        if (c.w != 0.f) {
            v = root_pilot[i * CAL_N + t];
        } else {
            float pv0 = xs[(pk & 0xff) * CAL_N + t];
            float pv1 = xs[((pk >> 8) & 0xff) * CAL_N + t];
            v = fmaxf(fmaf(c.x, pv0, fmaf(c.y, pv1, c.z)), 0.f);
        }
        xs[i * CAL_N + t] = v;
    }

    float my = xs[node * CAL_N + t];
    __syncthreads();

    const float* row = xs + node * CAL_N;
    int rank = 0;
    #pragma unroll 8
    for (int j = 0; j < CAL_N; j++) {
        float o = row[j];
        rank += (o < my) || (o == my && j < t);   // stable rank: bijection 0..255
    }
    if (rank == 63)  q[0] = my;
    if (rank == 64)  q[1] = my;
    if (rank == 191) q[2] = my;
    if (rank == 192) q[3] = my;
    __syncthreads();

    if (t == 0) {
        float q25 = q[0] + 0.75f * (q[1] - q[0]);
        float q75 = q[2] + 0.25f * (q[3] - q[2]);
        float sig = 0.1f * fmaxf(q75 - q25, 1e-6f);

        float m0 = pm[node * 2 + 0], m1 = pm[node * 2 + 1];
        bool  root = (m0 == 0.f) && (m1 == 0.f);
        // Byte offsets for main kernel: p*SPB*4 = p*256, max 32512 (fits u16)
        uint32_t p0 = (uint32_t)(pidx[node * 2 + 0] & 0xff) * (SPB * 4);
        uint32_t p1 = (uint32_t)(pidx[node * 2 + 1] & 0xff) * (SPB * 4);
        if (root) {
            g_cA[node]   = make_float4(0.f, 0.f, 0.f, 1.f);
            g_cPk[node]  = 0u;
            g_srcP[node] = rm + (size_t)node * n;
        } else {
            g_cA[node]   = make_float4(W[node * 2 + 0] * m0,
                                       W[node * 2 + 1] * m1,
                                       b[node], sig);
            g_cPk[node]  = p0 | (p1 << 16);
            g_srcP[node] = zn + (size_t)node * n;
        }
    }
}

// ---------------------------------------------------------------------------
// K2: main pass, float2-vectorized. 1 warp per block, 64 samples; thread t
// owns samples 2t, 2t+1 = an 8B private column slice of shv[node][64].
// Memory ops are 64-bit: cp.async 8B, LDS.64 stage/parent reads, STS.64
// result store -> HALF the LSU ops of the scalar R12 version (which was
// L1-issue bound at 76%), while smem/block stays 44KB -> 5 blocks/SM =
// 5 warps & 320 resident samples/SM (the float4 R13 version collapsed to
// 2 warps/SM, occ 3.1%). Stage slices thread-private -> zero __syncthreads
// in the mainloop. cp.async in flight: 5 x DEPTH(4) x 2KB = 40KB/SM.
//   v_i = relu(w0*pv0 + w1*pv1 + b) + sigma * src_i[s]
// Root: w=b=0, sigma=1 (fmaxf kills 0*garbage NaN) -> v = root_main exactly.
// ---------------------------------------------------------------------------
__global__ void __launch_bounds__(NTHR)
main_kernel(const int* __restrict__ chosen,
            float*     __restrict__ out,
            int n)
{
    extern __shared__ float shv[];         // [N_NODES][SPB] = 32 KB
    float* stage = shv + N_NODES * SPB;    // [DEPTH][CHUNK][SPB] = 8 KB
    __shared__ float4       cA[N_NODES];
    __shared__ uint32_t     cPk[N_NODES];
    __shared__ const float* srcP[N_NODES];
    __shared__ int          ch[N_OBS];

    int t  = threadIdx.x;
    int s0 = blockIdx.x * SPB;

    #pragma unroll
    for (int j = t; j < N_NODES; j += NTHR) {
        cA[j]   = g_cA[j];
        cPk[j]  = g_cPk[j];
        srcP[j] = g_srcP[j];
    }
    #pragma unroll
    for (int j = t; j < N_OBS; j += NTHR) ch[j] = chosen[j];
    __syncwarp();

    char* myCol = reinterpret_cast<char*>(shv) + t * 8;    // 8B column slice
    const uint32_t myStage = smem_u32(stage) + (uint32_t)t * 8;

    if (s0 + SPB <= n) {
        // thread-private 8B cp.async: thread t fills samples 2t,2t+1 of each row
        auto prefetch = [&](int c) {
            uint32_t dst = myStage + (uint32_t)(c & (DEPTH - 1)) * (CHUNK * SPB * 4);
            #pragma unroll
            for (int r = 0; r < CHUNK; r++) {
                const float* src = srcP[c * CHUNK + r] + s0 + 2 * t;  // 8B aligned
                asm volatile("cp.async.ca.shared.global [%0], [%1], 8;\n"
                             :: "r"(dst + r * (SPB * 4)), "l"(src) : "memory");
            }
            asm volatile("cp.async.commit_group;\n" ::: "memory");
        };
        auto consume = [&](int c) {
            const char* stg = reinterpret_cast<const char*>(stage)
                              + (c & (DEPTH - 1)) * (CHUNK * SPB * 4) + t * 8;
            #pragma unroll
            for (int u = 0; u < CHUNK; u++) {
                int i = c * CHUNK + u;
                float2   cur = *reinterpret_cast<const float2*>(stg + u * (SPB * 4));
                float4   cc  = cA[i];                 // uniform LDS.128 broadcast
                uint32_t pk  = cPk[i];
                float2 p0 = *reinterpret_cast<const float2*>(myCol + (pk & 0xffffu));
                float2 p1 = *reinterpret_cast<const float2*>(myCol + (pk >> 16));
                float2 r;
                r.x = fmaf(cc.w, cur.x, fmaxf(fmaf(cc.x, p0.x, fmaf(cc.y, p1.x, cc.z)), 0.f));
                r.y = fmaf(cc.w, cur.y, fmaxf(fmaf(cc.x, p0.y, fmaf(cc.y, p1.y, cc.z)), 0.f));
                *reinterpret_cast<float2*>(myCol + i * (SPB * 4)) = r;
            }
        };

        prefetch(0); prefetch(1); prefetch(2); prefetch(3);

        #pragma unroll 1
        for (int c = 0; c < NCHUNK - DEPTH; c++) {
            asm volatile("cp.async.wait_group %0;\n" :: "n"(DEPTH - 1) : "memory");
            consume(c);
            prefetch(c + DEPTH);
        }
        asm volatile("cp.async.wait_group 2;\n" ::: "memory"); consume(NCHUNK - 4);
        asm volatile("cp.async.wait_group 1;\n" ::: "memory"); consume(NCHUNK - 3);
        asm volatile("cp.async.wait_group 0;\n" ::: "memory");
        consume(NCHUNK - 2); consume(NCHUNK - 1);

        // Output: 2x4 transpose gather. Thread t owns output rows s0+2t, s0+2t+1.
        // Groups of 4 chosen nodes: 4x LDS.64 (own columns) -> 2x STG.128.
        #pragma unroll 4
        for (int j0 = 0; j0 < N_OBS / 4; j0++) {
            float2 v0 = *reinterpret_cast<const float2*>(myCol + ch[4*j0+0] * (SPB*4));
            float2 v1 = *reinterpret_cast<const float2*>(myCol + ch[4*j0+1] * (SPB*4));
            float2 v2 = *reinterpret_cast<const float2*>(myCol + ch[4*j0+2] * (SPB*4));
            float2 v3 = *reinterpret_cast<const float2*>(myCol + ch[4*j0+3] * (SPB*4));
            size_t base = (size_t)(s0 + 2 * t) * N_OBS + 4 * j0;
            *reinterpret_cast<float4*>(out + base)         = make_float4(v0.x, v1.x, v2.x, v3.x);
            *reinterpret_cast<float4*>(out + base + N_OBS) = make_float4(v0.y, v1.y, v2.y, v3.y);
        }
    } else {
        // ---- tail path (unused at n=262144, kept for generality) ----
        for (int k = 0; k < 2; k++) {
            int s = s0 + 2 * t + k;
            if (s >= n) break;
            for (int i = 0; i < N_NODES; i++) {
                float    cur = srcP[i][s];
                float4   cc  = cA[i];
                uint32_t pk  = cPk[i];
                float pv0 = *reinterpret_cast<float*>(myCol + (pk & 0xffffu) + 4 * k);
                float pv1 = *reinterpret_cast<float*>(myCol + (pk >> 16) + 4 * k);
                float h   = fmaxf(fmaf(cc.x, pv0, fmaf(cc.y, pv1, cc.z)), 0.f);
                *reinterpret_cast<float*>(myCol + i * (SPB * 4) + 4 * k) = fmaf(cc.w, cur, h);
            }
            for (int j = 0; j < N_OBS; j++)
                out[(size_t)s * N_OBS + j] = shv[ch[j] * SPB + 2 * t + k];
        }
    }
}

// ---------------------------------------------------------------------------
// Launch. Input order per setup_inputs dict:
// 0:n_samples 1:W 2:b 3:root_pilot 4:root_main 5:z_noise
// 6:par_mask 7:par_idx 8:is_root 9:chosen
// ---------------------------------------------------------------------------
extern "C" void kernel_launch(void* const* d_in, const int* in_sizes, int n_in,
                              void* d_out, int out_size)
{
    const float* W    = (const float*)d_in[1];
    const float* b    = (const float*)d_in[2];
    const float* rpil = (const float*)d_in[3];
    const float* rm   = (const float*)d_in[4];
    const float* zn   = (const float*)d_in[5];
    const float* pmsk = (const float*)d_in[6];
    const int*   pidx = (const int*)d_in[7];
    const int*   chos = (const int*)d_in[9];
    float*       out  = (float*)d_out;

    int n = in_sizes[4] / N_NODES;     // 262144

    const int calSmem  = N_NODES * CAL_N * sizeof(float);                    // 128 KB
    const int mainSmem = (N_NODES * SPB + DEPTH * CHUNK * SPB) * sizeof(float); // 40 KB

    cudaFuncSetAttribute(cal_kernel,
                         cudaFuncAttributeMaxDynamicSharedMemorySize, calSmem);

    cal_kernel<<<N_NODES, CAL_N, calSmem>>>(W, b, pmsk, pidx, rpil, rm, zn, n);

    int grid = (n + SPB - 1) / SPB;    // 4096
    main_kernel<<<grid, NTHR, mainSmem>>>(chos, out, n);
}

// round 17
// speedup vs baseline: 1.1465x; 1.0026x over previous
#include <cuda_runtime.h>
#include <cuda_bf16.h>
#include <cstdint>

// Problem constants (fixed by the reference setup)
#define N_NODES   128
#define CAL_N     256
#define N_OBS     64
#define SPB       64     // samples per block in main kernel
#define NTHR      32     // 1 warp; each thread owns 2 consecutive samples
#define CHUNK     4      // node-rows per staging chunk (small -> short period)
#define NCHUNK    (N_NODES / CHUNK)   // 32
#define DEPTH     8      // cp.async pipeline depth: period = lat/(DEPTH-1)

// Device scratch (allocation-free rule: __device__ globals)
__device__ float4       g_cA[N_NODES];   // {w0, w1, b, sigma} (root: {0,0,0,1})
__device__ uint32_t     g_cPk[N_NODES];  // (p0*SPB*4) | ((p1*SPB*4)<<16); UNSIGNED so
                                         // >>16 is a logical shift
__device__ const float* g_srcP[N_NODES]; // per-node source row: root->rm+i*n else zn+i*n

__device__ __forceinline__ uint32_t smem_u32(const void* p) {
    return (uint32_t)__cvta_generic_to_shared(p);
}

// ---------------------------------------------------------------------------
// K1 (fused cal): 128 blocks x 256 threads. EVERY block redundantly runs the
// noiseless pilot recurrence over [128 nodes][256 samples] in its own smem
// (identical FP ops -> identical result), then block b rank-counts its own
// node b and bakes the per-node constants for the main pass.
// jnp.quantile linear: q25 at 63.75 -> v[63]+0.75*(v[64]-v[63]),
//                      q75 at 191.25 -> v[191]+0.25*(v[192]-v[191]).
// ---------------------------------------------------------------------------
__global__ void __launch_bounds__(CAL_N)
cal_kernel(const float* __restrict__ W,
           const float* __restrict__ b,
           const float* __restrict__ pm,
           const int*   __restrict__ pidx,
           const float* __restrict__ root_pilot,
           const float* __restrict__ rm,
           const float* __restrict__ zn,
           int n)
{
    extern __shared__ float xs[];          // [N_NODES][CAL_N] = 128 KB
    __shared__ float4 pc[N_NODES];
    __shared__ int    pp[N_NODES];
    __shared__ float  q[4];

    int node = blockIdx.x;
    int t = threadIdx.x;

    if (t < N_NODES) {
        float m0 = pm[t * 2 + 0], m1 = pm[t * 2 + 1];
        bool  root = (m0 == 0.f) && (m1 == 0.f);
        pc[t] = make_float4(W[t * 2 + 0] * m0, W[t * 2 + 1] * m1,
                            b[t], root ? 1.f : 0.f);
        pp[t] = (pidx[t * 2 + 0] & 0xff) | ((pidx[t * 2 + 1] & 0xff) << 8);
    }
    __syncthreads();

    for (int i = 0; i < N_NODES; i++) {
        float4 c  = pc[i];
        int    pk = pp[i];
        float v;
        if (c.w != 0.f) {
            v = root_pilot[i * CAL_N + t];
        } else {
            float pv0 = xs[(pk & 0xff) * CAL_N + t];
            float pv1 = xs[((pk >> 8) & 0xff) * CAL_N + t];
            v = fmaxf(fmaf(c.x, pv0, fmaf(c.y, pv1, c.z)), 0.f);
        }
        xs[i * CAL_N + t] = v;
    }

    float my = xs[node * CAL_N + t];
    __syncthreads();

    const float* row = xs + node * CAL_N;
    int rank = 0;
    #pragma unroll 8
    for (int j = 0; j < CAL_N; j++) {
        float o = row[j];
        rank += (o < my) || (o == my && j < t);   // stable rank: bijection 0..255
    }
    if (rank == 63)  q[0] = my;
    if (rank == 64)  q[1] = my;
    if (rank == 191) q[2] = my;
    if (rank == 192) q[3] = my;
    __syncthreads();

    if (t == 0) {
        float q25 = q[0] + 0.75f * (q[1] - q[0]);
        float q75 = q[2] + 0.25f * (q[3] - q[2]);
        float sig = 0.1f * fmaxf(q75 - q25, 1e-6f);

        float m0 = pm[node * 2 + 0], m1 = pm[node * 2 + 1];
        bool  root = (m0 == 0.f) && (m1 == 0.f);
        // Byte offsets for main kernel: p*SPB*4 = p*256, max 32512 (fits u16)
        uint32_t p0 = (uint32_t)(pidx[node * 2 + 0] & 0xff) * (SPB * 4);
        uint32_t p1 = (uint32_t)(pidx[node * 2 + 1] & 0xff) * (SPB * 4);
        if (root) {
            g_cA[node]   = make_float4(0.f, 0.f, 0.f, 1.f);
            g_cPk[node]  = 0u;
            g_srcP[node] = rm + (size_t)node * n;
        } else {
            g_cA[node]   = make_float4(W[node * 2 + 0] * m0,
                                       W[node * 2 + 1] * m1,
                                       b[node], sig);
            g_cPk[node]  = p0 | (p1 << 16);
            g_srcP[node] = zn + (size_t)node * n;
        }
    }
}

// ---------------------------------------------------------------------------
// K2: main pass, float2-vectorized, DEEP cp.async pipeline. 1 warp per block,
// 64 samples; thread t owns samples 2t,2t+1 = an 8B private column slice.
// R12/R13/R15 all pinned at ~82us regardless of LSU-instruction count -> the
// bound is the pipeline period max(consume, lat/(DEPTH-1)). With DEPTH=4 and
// lat~1000cyc @NAT, period ~333cyc was memory-side bound. DEPTH=8 + CHUNK=4
// gives period = max(~100, lat/7 ~143) -> consume-side, same smem (stage 8KB,
// 44KB/block -> 5 blocks/SM). In flight: 5 x 7 x 1KB = 35KB/SM.
//   v_i = relu(w0*pv0 + w1*pv1 + b) + sigma * src_i[s]
// Root: w=b=0, sigma=1 (fmaxf kills 0*garbage NaN) -> v = root_main exactly.
// ---------------------------------------------------------------------------
__global__ void __launch_bounds__(NTHR)
main_kernel(const int* __restrict__ chosen,
            float*     __restrict__ out,
            int n)
{
    extern __shared__ float shv[];         // [N_NODES][SPB] = 32 KB
    float* stage = shv + N_NODES * SPB;    // [DEPTH][CHUNK][SPB] = 8 KB
    __shared__ float4       cA[N_NODES];
    __shared__ uint32_t     cPk[N_NODES];
    __shared__ const float* srcP[N_NODES];
    __shared__ int          ch[N_OBS];

    int t  = threadIdx.x;
    int s0 = blockIdx.x * SPB;

    #pragma unroll
    for (int j = t; j < N_NODES; j += NTHR) {
        cA[j]   = g_cA[j];
        cPk[j]  = g_cPk[j];
        srcP[j] = g_srcP[j];
    }
    #pragma unroll
    for (int j = t; j < N_OBS; j += NTHR) ch[j] = chosen[j];
    __syncwarp();

    char* myCol = reinterpret_cast<char*>(shv) + t * 8;    // 8B column slice
    const uint32_t myStage = smem_u32(stage) + (uint32_t)t * 8;

    if (s0 + SPB <= n) {
        // thread-private 8B cp.async: thread t fills samples 2t,2t+1 of each row
        auto prefetch = [&](int c) {
            uint32_t dst = myStage + (uint32_t)(c & (DEPTH - 1)) * (CHUNK * SPB * 4);
            #pragma unroll
            for (int r = 0; r < CHUNK; r++) {
                const float* src = srcP[c * CHUNK + r] + s0 + 2 * t;  // 8B aligned
                asm volatile("cp.async.ca.shared.global [%0], [%1], 8;\n"
                             :: "r"(dst + r * (SPB * 4)), "l"(src) : "memory");
            }
            asm volatile("cp.async.commit_group;\n" ::: "memory");
        };
        auto consume = [&](int c) {
            const char* stg = reinterpret_cast<const char*>(stage)
                              + (c & (DEPTH - 1)) * (CHUNK * SPB * 4) + t * 8;
            #pragma unroll
            for (int u = 0; u < CHUNK; u++) {
                int i = c * CHUNK + u;
                float2   cur = *reinterpret_cast<const float2*>(stg + u * (SPB * 4));
                float4   cc  = cA[i];                 // uniform LDS.128 broadcast
                uint32_t pk  = cPk[i];
                float2 p0 = *reinterpret_cast<const float2*>(myCol + (pk & 0xffffu));
                float2 p1 = *reinterpret_cast<const float2*>(myCol + (pk >> 16));
                float2 r;
                r.x = fmaf(cc.w, cur.x, fmaxf(fmaf(cc.x, p0.x, fmaf(cc.y, p1.x, cc.z)), 0.f));
                r.y = fmaf(cc.w, cur.y, fmaxf(fmaf(cc.x, p0.y, fmaf(cc.y, p1.y, cc.z)), 0.f));
                *reinterpret_cast<float2*>(myCol + i * (SPB * 4)) = r;
            }
        };

        prefetch(0); prefetch(1); prefetch(2); prefetch(3);
        prefetch(4); prefetch(5); prefetch(6); prefetch(7);

        #pragma unroll 1
        for (int c = 0; c < NCHUNK - DEPTH; c++) {
            asm volatile("cp.async.wait_group %0;\n" :: "n"(DEPTH - 1) : "memory");
            consume(c);
            prefetch(c + DEPTH);
        }
        // Drain tail: 8 remaining chunks, progressively fewer pending groups.
        asm volatile("cp.async.wait_group 6;\n" ::: "memory"); consume(NCHUNK - 8);
        asm volatile("cp.async.wait_group 5;\n" ::: "memory"); consume(NCHUNK - 7);
        asm volatile("cp.async.wait_group 4;\n" ::: "memory"); consume(NCHUNK - 6);
        asm volatile("cp.async.wait_group 3;\n" ::: "memory"); consume(NCHUNK - 5);
        asm volatile("cp.async.wait_group 2;\n" ::: "memory"); consume(NCHUNK - 4);
        asm volatile("cp.async.wait_group 1;\n" ::: "memory"); consume(NCHUNK - 3);
        asm volatile("cp.async.wait_group 0;\n" ::: "memory");
        consume(NCHUNK - 2); consume(NCHUNK - 1);

        // Output: 2x4 transpose gather. Thread t owns output rows s0+2t, s0+2t+1.
        // Groups of 4 chosen nodes: 4x LDS.64 (own columns) -> 2x STG.128.
        #pragma unroll 4
        for (int j0 = 0; j0 < N_OBS / 4; j0++) {
            float2 v0 = *reinterpret_cast<const float2*>(myCol + ch[4*j0+0] * (SPB*4));
            float2 v1 = *reinterpret_cast<const float2*>(myCol + ch[4*j0+1] * (SPB*4));
            float2 v2 = *reinterpret_cast<const float2*>(myCol + ch[4*j0+2] * (SPB*4));
            float2 v3 = *reinterpret_cast<const float2*>(myCol + ch[4*j0+3] * (SPB*4));
            size_t base = (size_t)(s0 + 2 * t) * N_OBS + 4 * j0;
            *reinterpret_cast<float4*>(out + base)         = make_float4(v0.x, v1.x, v2.x, v3.x);
            *reinterpret_cast<float4*>(out + base + N_OBS) = make_float4(v0.y, v1.y, v2.y, v3.y);
        }
    } else {
        // ---- tail path (unused at n=262144, kept for generality) ----
        for (int k = 0; k < 2; k++) {
            int s = s0 + 2 * t + k;
            if (s >= n) break;
            for (int i = 0; i < N_NODES; i++) {
                float    cur = srcP[i][s];
                float4   cc  = cA[i];
                uint32_t pk  = cPk[i];
                float pv0 = *reinterpret_cast<float*>(myCol + (pk & 0xffffu) + 4 * k);
                float pv1 = *reinterpret_cast<float*>(myCol + (pk >> 16) + 4 * k);
                float h   = fmaxf(fmaf(cc.x, pv0, fmaf(cc.y, pv1, cc.z)), 0.f);
                *reinterpret_cast<float*>(myCol + i * (SPB * 4) + 4 * k) = fmaf(cc.w, cur, h);
            }
            for (int j = 0; j < N_OBS; j++)
                out[(size_t)s * N_OBS + j] = shv[ch[j] * SPB + 2 * t + k];
        }
    }
}

// ---------------------------------------------------------------------------
// Launch. Input order per setup_inputs dict:
// 0:n_samples 1:W 2:b 3:root_pilot 4:root_main 5:z_noise
// 6:par_mask 7:par_idx 8:is_root 9:chosen
// ---------------------------------------------------------------------------
extern "C" void kernel_launch(void* const* d_in, const int* in_sizes, int n_in,
                              void* d_out, int out_size)
{
    const float* W    = (const float*)d_in[1];
    const float* b    = (const float*)d_in[2];
    const float* rpil = (const float*)d_in[3];
    const float* rm   = (const float*)d_in[4];
    const float* zn   = (const float*)d_in[5];
    const float* pmsk = (const float*)d_in[6];
    const int*   pidx = (const int*)d_in[7];
    const int*   chos = (const int*)d_in[9];
    float*       out  = (float*)d_out;

    int n = in_sizes[4] / N_NODES;     // 262144

    const int calSmem  = N_NODES * CAL_N * sizeof(float);                    // 128 KB
    const int mainSmem = (N_NODES * SPB + DEPTH * CHUNK * SPB) * sizeof(float); // 40 KB

    cudaFuncSetAttribute(cal_kernel,
                         cudaFuncAttributeMaxDynamicSharedMemorySize, calSmem);

    cal_kernel<<<N_NODES, CAL_N, calSmem>>>(W, b, pmsk, pidx, rpil, rm, zn, n);

    int grid = (n + SPB - 1) / SPB;    // 4096
    main_kernel<<<grid, NTHR, mainSmem>>>(chos, out, n);
}